// round 10
// baseline (speedup 1.0000x reference)
#include <cuda_runtime.h>
#include <cuda_fp16.h>
#include <cstdint>

// out = x @ W^T (GAT attention cancels: softmax rows sum to 1; final einsum
// multiplies h by sum_j alpha = 1; adj/a_w dead).  M=8192, N=256, K=256, NT.
//
// Single fused kernel. Full-K resident tiles (A 64x256, B 128x256 fp16 in
// smem), fp32->fp16 conversion inline in the prologue (batched LDG with
// overlap), ONE barrier, then 16 unrolled ldsm+mma k-steps with fragment
// double-buffering and no syncs.

#define THREADS 256
#define BM 64
#define BN 128
#define KGLOB 256
#define A_TILE_B 8192           // per-k-chunk A tile: 64 rows x 128B
#define B_TILE_B 16384          // per-k-chunk B tile: 128 rows x 128B
#define SA_BYTES (4 * A_TILE_B) // 32KB
#define SB_BYTES (4 * B_TILE_B) // 64KB
#define SMEM_TOTAL (SA_BYTES + SB_BYTES)   // 96KB -> 2 CTAs/SM

__device__ __forceinline__ uint32_t smem_u32(const void* p) {
    uint32_t a;
    asm("{ .reg .u64 t; cvta.to.shared.u64 t, %1; cvt.u32.u64 %0, t; }" : "=r"(a) : "l"(p));
    return a;
}
__device__ __forceinline__ uint32_t swz(uint32_t off) { return off ^ ((off >> 3) & 0x70); }

__device__ __forceinline__ void ldsm4(uint32_t* r, uint32_t addr) {
    asm volatile("ldmatrix.sync.aligned.m8n8.x4.shared.b16 {%0,%1,%2,%3}, [%4];"
                 : "=r"(r[0]), "=r"(r[1]), "=r"(r[2]), "=r"(r[3]) : "r"(addr));
}
__device__ __forceinline__ void ldsm2x2(uint32_t* r0, uint32_t* r1, uint32_t addr) {
    asm volatile("ldmatrix.sync.aligned.m8n8.x4.shared.b16 {%0,%1,%2,%3}, [%4];"
                 : "=r"(r0[0]), "=r"(r0[1]), "=r"(r1[0]), "=r"(r1[1]) : "r"(addr));
}
__device__ __forceinline__ void mma16816(float* c, const uint32_t* a, const uint32_t* b) {
    asm volatile("mma.sync.aligned.m16n8k16.row.col.f32.f16.f16.f32 "
                 "{%0,%1,%2,%3}, {%4,%5,%6,%7}, {%8,%9}, {%0,%1,%2,%3};"
                 : "+f"(c[0]), "+f"(c[1]), "+f"(c[2]), "+f"(c[3])
                 : "r"(a[0]), "r"(a[1]), "r"(a[2]), "r"(a[3]), "r"(b[0]), "r"(b[1]));
}
__device__ __forceinline__ uint32_t pack2(float x, float y) {
    __half2 h = __floats2half2_rn(x, y);
    return *reinterpret_cast<uint32_t*>(&h);
}

__global__ void __launch_bounds__(THREADS)
gat_fused(const float* __restrict__ A, const float* __restrict__ B, float* __restrict__ C)
{
    extern __shared__ __align__(1024) uint8_t smem[];
    uint8_t* sA = smem;               // 4 x 8KB k-chunk tiles
    uint8_t* sB = smem + SA_BYTES;    // 4 x 16KB k-chunk tiles

    const int tid = threadIdx.x;
    const int wid = tid >> 5;
    const int lid = tid & 31;
    const int bm = blockIdx.y, bn = blockIdx.x;
    const int wm = wid & 1;           // 2 warp rows of 32
    const int wn = wid >> 1;          // 4 warp cols of 32

    const float* Ag = A + (size_t)(bm * BM) * KGLOB;
    const float* Bg = B + (size_t)(bn * BN) * KGLOB;   // W, fp32

    // ================= prologue: convert both operands into smem ============
    // B: 128 rows x 64 float4; 2 threads/row, 8 float4/thread/chunk (4 chunks)
    // A:  64 rows x 64 float4; 4 threads/row, 8 float4/thread/batch (2 batches)
    const int br = tid >> 1, bs = tid & 1;
    const int ar = tid >> 2, as = tid & 3;

    float4 t0[8], t1[8];

    auto ldB = [&](int c, float4* t) {
#pragma unroll
        for (int i = 0; i < 8; i++)
            t[i] = *(const float4*)(Bg + (size_t)br * KGLOB + c * 64 + (8 * bs + i) * 4);
    };
    auto stB = [&](int c, const float4* t) {
        uint8_t* tile = sB + c * B_TILE_B;
#pragma unroll
        for (int i = 0; i < 8; i++) {
            uint2 p;
            p.x = pack2(t[i].x, t[i].y);
            p.y = pack2(t[i].z, t[i].w);
            *(uint2*)(tile + swz((uint32_t)(br * 128 + (8 * bs + i) * 8))) = p;
        }
    };
    auto ldA = [&](int j, float4* t) {
#pragma unroll
        for (int i = 0; i < 8; i++) {
            int slot = as + 4 * (8 * j + i);    // 0..63
            t[i] = *(const float4*)(Ag + (size_t)ar * KGLOB + slot * 4);
        }
    };
    auto stA = [&](int j, const float4* t) {
#pragma unroll
        for (int i = 0; i < 8; i++) {
            int slot = as + 4 * (8 * j + i);
            uint8_t* tile = sA + (slot >> 4) * A_TILE_B;
            uint2 p;
            p.x = pack2(t[i].x, t[i].y);
            p.y = pack2(t[i].z, t[i].w);
            *(uint2*)(tile + swz((uint32_t)(ar * 128 + (slot & 15) * 8))) = p;
        }
    };

    // overlap: issue next batch's LDGs before converting/storing current
    ldB(0, t0);
    ldB(1, t1); stB(0, t0);
    ldB(2, t0); stB(1, t1);
    ldB(3, t1); stB(2, t0);
    ldA(0, t0); stB(3, t1);
    ldA(1, t1); stA(0, t0);
    stA(1, t1);
    __syncthreads();    // the only barrier

    // ================= MMA: 16 unrolled k-steps, frag double-buffer =========
    float acc[2][4][4];
#pragma unroll
    for (int i = 0; i < 2; i++)
#pragma unroll
        for (int j = 0; j < 4; j++)
#pragma unroll
            for (int k = 0; k < 4; k++) acc[i][j][k] = 0.f;

    const uint32_t a_row = (lid & 15);
    const uint32_t a_cb  = (lid >> 4) * 16;
    const uint32_t b_row = (lid & 7) + ((lid >> 4) << 3);
    const uint32_t b_cb  = ((lid >> 3) & 1) * 16;
    const uint32_t sAb = smem_u32(sA);
    const uint32_t sBb = smem_u32(sB);

    uint32_t af[2][2][4];     // [buf][mt][reg]
    uint32_t bf[2][4][2];     // [buf][nt][reg]

    auto fetch = [&](int ks, int buf) {
        const uint32_t kb = (uint32_t)(ks & 3) * 32;
        const uint32_t tA = (uint32_t)(ks >> 2) * A_TILE_B;
        const uint32_t tB = (uint32_t)(ks >> 2) * B_TILE_B;
#pragma unroll
        for (int mt = 0; mt < 2; mt++)
            ldsm4(af[buf][mt],
                  sAb + tA + swz((wm * 32 + mt * 16 + a_row) * 128 + kb + a_cb));
#pragma unroll
        for (int ntp = 0; ntp < 2; ntp++)
            ldsm2x2(bf[buf][2 * ntp], bf[buf][2 * ntp + 1],
                    sBb + tB + swz((wn * 32 + ntp * 16 + b_row) * 128 + kb + b_cb));
    };

    fetch(0, 0);
#pragma unroll
    for (int ks = 0; ks < 16; ks++) {
        const int cur = ks & 1;
        if (ks < 15) fetch(ks + 1, cur ^ 1);
#pragma unroll
        for (int mt = 0; mt < 2; mt++)
#pragma unroll
            for (int nt = 0; nt < 4; nt++)
                mma16816(acc[mt][nt], af[cur][mt], bf[cur][nt]);
    }

    // ================= epilogue ============================================
    const int g = lid >> 2, tig = lid & 3;
#pragma unroll
    for (int mt = 0; mt < 2; mt++) {
#pragma unroll
        for (int nt = 0; nt < 4; nt++) {
            int row = bm * BM + wm * 32 + mt * 16 + g;
            int col = bn * BN + wn * 32 + nt * 8 + 2 * tig;
            *(float2*)(C + (size_t)row * 256 + col) = make_float2(acc[mt][nt][0], acc[mt][nt][1]);
            *(float2*)(C + (size_t)(row + 8) * 256 + col) = make_float2(acc[mt][nt][2], acc[mt][nt][3]);
        }
    }
}

extern "C" void kernel_launch(void* const* d_in, const int* in_sizes, int n_in,
                              void* d_out, int out_size)
{
    const float* x = (const float*)d_in[0];
    const float* W = (const float*)d_in[2];
    float* out = (float*)d_out;

    cudaFuncSetAttribute(gat_fused, cudaFuncAttributeMaxDynamicSharedMemorySize, SMEM_TOTAL);
    dim3 grid(256 / BN, 8192 / BM);   // (2, 128) = 256 CTAs
    gat_fused<<<grid, THREADS, SMEM_TOTAL>>>(x, W, out);
}

// round 11
// speedup vs baseline: 1.6375x; 1.6375x over previous
#include <cuda_runtime.h>
#include <cuda_fp16.h>
#include <cstdint>

// out = x @ W^T (GAT attention cancels: softmax rows sum to 1; final einsum
// multiplies h by sum_j alpha = 1; adj/a_w dead).  M=8192, N=256, K=256, NT.
//
// R8/R10 lesson: inline fp32->fp16 conversion inside the GEMM poisons it
// (register staging + L1 pressure). R7 lesson: cp.async GEMM on fp16 inputs
// is fast; its convert pre-pass was just badly written.
// Plan: (1) fast wide convert kernel (x+W -> fp16 scratch, ~2us),
//       (2) single-shot cp.async full-K GEMM, one barrier, unrolled MMA.

#define THREADS 256
#define BM 64
#define BN 128
#define KGLOB 256
#define A_TILE_B 8192           // k-chunk A tile: 64 rows x 128B
#define B_TILE_B 16384          // k-chunk B tile: 128 rows x 128B
#define SA_BYTES (4 * A_TILE_B) // 32KB
#define SB_BYTES (4 * B_TILE_B) // 64KB
#define SMEM_TOTAL (SA_BYTES + SB_BYTES)   // 96KB -> 2 CTAs/SM

__device__ __align__(16) __half g_xh[8192 * 256];
__device__ __align__(16) __half g_wh[256 * 256];

__device__ __forceinline__ uint32_t smem_u32(const void* p) {
    uint32_t a;
    asm("{ .reg .u64 t; cvta.to.shared.u64 t, %1; cvt.u32.u64 %0, t; }" : "=r"(a) : "l"(p));
    return a;
}
__device__ __forceinline__ uint32_t swz(uint32_t off) { return off ^ ((off >> 3) & 0x70); }

__device__ __forceinline__ void cp16(uint32_t dst, const void* src) {
    asm volatile("cp.async.cg.shared.global [%0], [%1], 16;" :: "r"(dst), "l"(src) : "memory");
}
__device__ __forceinline__ void cp_commit() {
    asm volatile("cp.async.commit_group;" ::: "memory");
}
__device__ __forceinline__ void cp_wait0() {
    asm volatile("cp.async.wait_group 0;" ::: "memory");
}

__device__ __forceinline__ void ldsm4(uint32_t* r, uint32_t addr) {
    asm volatile("ldmatrix.sync.aligned.m8n8.x4.shared.b16 {%0,%1,%2,%3}, [%4];"
                 : "=r"(r[0]), "=r"(r[1]), "=r"(r[2]), "=r"(r[3]) : "r"(addr));
}
__device__ __forceinline__ void ldsm2x2(uint32_t* r0, uint32_t* r1, uint32_t addr) {
    asm volatile("ldmatrix.sync.aligned.m8n8.x4.shared.b16 {%0,%1,%2,%3}, [%4];"
                 : "=r"(r0[0]), "=r"(r0[1]), "=r"(r1[0]), "=r"(r1[1]) : "r"(addr));
}
__device__ __forceinline__ void mma16816(float* c, const uint32_t* a, const uint32_t* b) {
    asm volatile("mma.sync.aligned.m16n8k16.row.col.f32.f16.f16.f32 "
                 "{%0,%1,%2,%3}, {%4,%5,%6,%7}, {%8,%9}, {%0,%1,%2,%3};"
                 : "+f"(c[0]), "+f"(c[1]), "+f"(c[2]), "+f"(c[3])
                 : "r"(a[0]), "r"(a[1]), "r"(a[2]), "r"(a[3]), "r"(b[0]), "r"(b[1]));
}
__device__ __forceinline__ uint32_t pack2(float x, float y) {
    __half2 h = __floats2half2_rn(x, y);
    return *reinterpret_cast<uint32_t*>(&h);
}

// ---------- convert x and W to fp16, wide (32 floats/thread) ----------
// blocks 0..255 -> x (1024 uint4 outputs each), blocks 256..263 -> W.
__global__ void __launch_bounds__(256)
cvt_all(const float4* __restrict__ x, const float4* __restrict__ w)
{
    const int b = blockIdx.x;
    const int t = threadIdx.x;
    const float4* src;
    uint4* dst;
    int outBase;
    if (b < 256) { src = x; dst = (uint4*)g_xh; outBase = b * 1024; }
    else         { src = w; dst = (uint4*)g_wh; outBase = (b - 256) * 1024; }

    float4 v[8];
#pragma unroll
    for (int i = 0; i < 4; i++) {
        int oi = outBase + t + i * 256;
        v[2 * i]     = src[2 * oi];
        v[2 * i + 1] = src[2 * oi + 1];
    }
#pragma unroll
    for (int i = 0; i < 4; i++) {
        uint4 p;
        p.x = pack2(v[2 * i].x,     v[2 * i].y);
        p.y = pack2(v[2 * i].z,     v[2 * i].w);
        p.z = pack2(v[2 * i + 1].x, v[2 * i + 1].y);
        p.w = pack2(v[2 * i + 1].z, v[2 * i + 1].w);
        dst[outBase + t + i * 256] = p;
    }
}

// ---------- GEMM: single-shot cp.async, one barrier, unrolled MMA ----------
__global__ void __launch_bounds__(THREADS)
gat_gemm4(float* __restrict__ C)
{
    extern __shared__ __align__(1024) uint8_t smem[];
    uint8_t* sA = smem;               // 4 x 8KB
    uint8_t* sB = smem + SA_BYTES;    // 4 x 16KB

    const int tid = threadIdx.x;
    const int wid = tid >> 5;
    const int lid = tid & 31;
    const int bm = blockIdx.y, bn = blockIdx.x;
    const int wm = wid & 1;           // 2 warp rows of 32
    const int wn = wid >> 1;          // 4 warp cols of 32

    const __half* Agh = g_xh + (size_t)(bm * BM) * KGLOB;
    const __half* Bgh = g_wh + (size_t)(bn * BN) * KGLOB;

    // prologue: 24 independent cp.async per thread (8 A + 16 B), one group
    {
        const int r  = tid >> 3;      // 0..31
        const int sl = tid & 7;       // 16B slot
#pragma unroll
        for (int c = 0; c < 4; c++) {
            uint8_t* tA = sA + c * A_TILE_B;
#pragma unroll
            for (int i = 0; i < 2; i++) {
                int rr = r + i * 32;
                cp16(smem_u32(tA + swz((uint32_t)(rr * 128 + sl * 16))),
                     Agh + (size_t)rr * KGLOB + c * 64 + sl * 8);
            }
            uint8_t* tB = sB + c * B_TILE_B;
#pragma unroll
            for (int i = 0; i < 4; i++) {
                int rr = r + i * 32;
                cp16(smem_u32(tB + swz((uint32_t)(rr * 128 + sl * 16))),
                     Bgh + (size_t)rr * KGLOB + c * 64 + sl * 8);
            }
        }
        cp_commit();
    }
    cp_wait0();
    __syncthreads();    // the only barrier

    float acc[2][4][4];
#pragma unroll
    for (int i = 0; i < 2; i++)
#pragma unroll
        for (int j = 0; j < 4; j++)
#pragma unroll
            for (int k = 0; k < 4; k++) acc[i][j][k] = 0.f;

    const uint32_t a_row = (lid & 15);
    const uint32_t a_cb  = (lid >> 4) * 16;
    const uint32_t b_row = (lid & 7) + ((lid >> 4) << 3);
    const uint32_t b_cb  = ((lid >> 3) & 1) * 16;
    const uint32_t sAb = smem_u32(sA);
    const uint32_t sBb = smem_u32(sB);

    uint32_t af[2][2][4];
    uint32_t bf[2][4][2];

    auto fetch = [&](int ks, int buf) {
        const uint32_t kb = (uint32_t)(ks & 3) * 32;
        const uint32_t tA = (uint32_t)(ks >> 2) * A_TILE_B;
        const uint32_t tB = (uint32_t)(ks >> 2) * B_TILE_B;
#pragma unroll
        for (int mt = 0; mt < 2; mt++)
            ldsm4(af[buf][mt],
                  sAb + tA + swz((wm * 32 + mt * 16 + a_row) * 128 + kb + a_cb));
#pragma unroll
        for (int ntp = 0; ntp < 2; ntp++)
            ldsm2x2(bf[buf][2 * ntp], bf[buf][2 * ntp + 1],
                    sBb + tB + swz((wn * 32 + ntp * 16 + b_row) * 128 + kb + b_cb));
    };

    fetch(0, 0);
#pragma unroll
    for (int ks = 0; ks < 16; ks++) {
        const int cur = ks & 1;
        if (ks < 15) fetch(ks + 1, cur ^ 1);
#pragma unroll
        for (int mt = 0; mt < 2; mt++)
#pragma unroll
            for (int nt = 0; nt < 4; nt++)
                mma16816(acc[mt][nt], af[cur][mt], bf[cur][nt]);
    }

    const int g = lid >> 2, tig = lid & 3;
#pragma unroll
    for (int mt = 0; mt < 2; mt++) {
#pragma unroll
        for (int nt = 0; nt < 4; nt++) {
            int row = bm * BM + wm * 32 + mt * 16 + g;
            int col = bn * BN + wn * 32 + nt * 8 + 2 * tig;
            *(float2*)(C + (size_t)row * 256 + col) = make_float2(acc[mt][nt][0], acc[mt][nt][1]);
            *(float2*)(C + (size_t)(row + 8) * 256 + col) = make_float2(acc[mt][nt][2], acc[mt][nt][3]);
        }
    }
}

extern "C" void kernel_launch(void* const* d_in, const int* in_sizes, int n_in,
                              void* d_out, int out_size)
{
    const float* x = (const float*)d_in[0];
    const float* W = (const float*)d_in[2];
    float* out = (float*)d_out;

    cvt_all<<<264, 256>>>((const float4*)x, (const float4*)W);

    cudaFuncSetAttribute(gat_gemm4, cudaFuncAttributeMaxDynamicSharedMemorySize, SMEM_TOTAL);
    dim3 grid(256 / BN, 8192 / BM);   // (2, 128) = 256 CTAs
    gat_gemm4<<<grid, THREADS, SMEM_TOTAL>>>(out);
}

// round 15
// speedup vs baseline: 1.6925x; 1.0336x over previous
#include <cuda_runtime.h>
#include <cuda_fp16.h>
#include <cstdint>

// out = x @ W^T (GAT attention cancels: softmax rows sum to 1; final einsum
// multiplies h by sum_j alpha = 1; adj/a_w dead).  M=8192, N=256, K=256, NT.
//
// Two kernels: (1) wide fp32->fp16 convert of x and W; (2) GEMM with a
// PROGRESSIVE cp.async pipeline: 4 commit groups (one per K-chunk), MMA on
// chunk c starts as soon as group c lands (wait_group 3/2/1/0), so chunks
// 1-3 stream behind tensor work instead of being exposed up front (R11 bug).

#define THREADS 256
#define BM 64
#define BN 128
#define KGLOB 256
#define A_TILE_B 8192           // k-chunk A tile: 64 rows x 128B
#define B_TILE_B 16384          // k-chunk B tile: 128 rows x 128B
#define SA_BYTES (4 * A_TILE_B) // 32KB
#define SB_BYTES (4 * B_TILE_B) // 64KB
#define SMEM_TOTAL (SA_BYTES + SB_BYTES)   // 96KB -> 2 CTAs/SM

__device__ __align__(16) __half g_xh[8192 * 256];
__device__ __align__(16) __half g_wh[256 * 256];

__device__ __forceinline__ uint32_t smem_u32(const void* p) {
    uint32_t a;
    asm("{ .reg .u64 t; cvta.to.shared.u64 t, %1; cvt.u32.u64 %0, t; }" : "=r"(a) : "l"(p));
    return a;
}
__device__ __forceinline__ uint32_t swz(uint32_t off) { return off ^ ((off >> 3) & 0x70); }

__device__ __forceinline__ void cp16(uint32_t dst, const void* src) {
    asm volatile("cp.async.cg.shared.global [%0], [%1], 16;" :: "r"(dst), "l"(src) : "memory");
}
__device__ __forceinline__ void cp_commit() {
    asm volatile("cp.async.commit_group;" ::: "memory");
}
template <int N>
__device__ __forceinline__ void cp_wait() {
    asm volatile("cp.async.wait_group %0;" :: "n"(N) : "memory");
}

__device__ __forceinline__ void ldsm4(uint32_t* r, uint32_t addr) {
    asm volatile("ldmatrix.sync.aligned.m8n8.x4.shared.b16 {%0,%1,%2,%3}, [%4];"
                 : "=r"(r[0]), "=r"(r[1]), "=r"(r[2]), "=r"(r[3]) : "r"(addr));
}
__device__ __forceinline__ void ldsm2x2(uint32_t* r0, uint32_t* r1, uint32_t addr) {
    asm volatile("ldmatrix.sync.aligned.m8n8.x4.shared.b16 {%0,%1,%2,%3}, [%4];"
                 : "=r"(r0[0]), "=r"(r0[1]), "=r"(r1[0]), "=r"(r1[1]) : "r"(addr));
}
__device__ __forceinline__ void mma16816(float* c, const uint32_t* a, const uint32_t* b) {
    asm volatile("mma.sync.aligned.m16n8k16.row.col.f32.f16.f16.f32 "
                 "{%0,%1,%2,%3}, {%4,%5,%6,%7}, {%8,%9}, {%0,%1,%2,%3};"
                 : "+f"(c[0]), "+f"(c[1]), "+f"(c[2]), "+f"(c[3])
                 : "r"(a[0]), "r"(a[1]), "r"(a[2]), "r"(a[3]), "r"(b[0]), "r"(b[1]));
}
__device__ __forceinline__ uint32_t pack2(float x, float y) {
    __half2 h = __floats2half2_rn(x, y);
    return *reinterpret_cast<uint32_t*>(&h);
}

// ---------- convert x and W to fp16, wide (32 floats/thread) ----------
__global__ void __launch_bounds__(256)
cvt_all(const float4* __restrict__ x, const float4* __restrict__ w)
{
    const int b = blockIdx.x;
    const int t = threadIdx.x;
    const float4* src;
    uint4* dst;
    int outBase;
    if (b < 256) { src = x; dst = (uint4*)g_xh; outBase = b * 1024; }
    else         { src = w; dst = (uint4*)g_wh; outBase = (b - 256) * 1024; }

    float4 v[8];
#pragma unroll
    for (int i = 0; i < 4; i++) {
        int oi = outBase + t + i * 256;
        v[2 * i]     = src[2 * oi];
        v[2 * i + 1] = src[2 * oi + 1];
    }
#pragma unroll
    for (int i = 0; i < 4; i++) {
        uint4 p;
        p.x = pack2(v[2 * i].x,     v[2 * i].y);
        p.y = pack2(v[2 * i].z,     v[2 * i].w);
        p.z = pack2(v[2 * i + 1].x, v[2 * i + 1].y);
        p.w = pack2(v[2 * i + 1].z, v[2 * i + 1].w);
        dst[outBase + t + i * 256] = p;
    }
}

// ---------- GEMM: progressive 4-group cp.async pipeline ----------
__global__ void __launch_bounds__(THREADS)
gat_gemm5(float* __restrict__ C)
{
    extern __shared__ __align__(1024) uint8_t smem[];
    uint8_t* sA = smem;               // 4 x 8KB
    uint8_t* sB = smem + SA_BYTES;    // 4 x 16KB

    const int tid = threadIdx.x;
    const int wid = tid >> 5;
    const int lid = tid & 31;
    const int bm = blockIdx.y, bn = blockIdx.x;
    const int wm = wid & 1;           // 2 warp rows of 32
    const int wn = wid >> 1;          // 4 warp cols of 32

    const __half* Agh = g_xh + (size_t)(bm * BM) * KGLOB;
    const __half* Bgh = g_wh + (size_t)(bn * BN) * KGLOB;

    // issue 4 commit groups, one per K-chunk, in consumption order
    {
        const int r  = tid >> 3;      // 0..31
        const int sl = tid & 7;       // 16B slot
#pragma unroll
        for (int c = 0; c < 4; c++) {
            uint8_t* tA = sA + c * A_TILE_B;
#pragma unroll
            for (int i = 0; i < 2; i++) {
                int rr = r + i * 32;
                cp16(smem_u32(tA + swz((uint32_t)(rr * 128 + sl * 16))),
                     Agh + (size_t)rr * KGLOB + c * 64 + sl * 8);
            }
            uint8_t* tB = sB + c * B_TILE_B;
#pragma unroll
            for (int i = 0; i < 4; i++) {
                int rr = r + i * 32;
                cp16(smem_u32(tB + swz((uint32_t)(rr * 128 + sl * 16))),
                     Bgh + (size_t)rr * KGLOB + c * 64 + sl * 8);
            }
            cp_commit();
        }
    }

    float acc[2][4][4];
#pragma unroll
    for (int i = 0; i < 2; i++)
#pragma unroll
        for (int j = 0; j < 4; j++)
#pragma unroll
            for (int k = 0; k < 4; k++) acc[i][j][k] = 0.f;

    const uint32_t a_row = (lid & 15);
    const uint32_t a_cb  = (lid >> 4) * 16;
    const uint32_t b_row = (lid & 7) + ((lid >> 4) << 3);
    const uint32_t b_cb  = ((lid >> 3) & 1) * 16;
    const uint32_t sAb = smem_u32(sA);
    const uint32_t sBb = smem_u32(sB);

    uint32_t af[2][2][4];
    uint32_t bf[2][4][2];

    auto fetch = [&](int ks, int buf) {
        const uint32_t kb = (uint32_t)(ks & 3) * 32;
        const uint32_t tA = (uint32_t)(ks >> 2) * A_TILE_B;
        const uint32_t tB = (uint32_t)(ks >> 2) * B_TILE_B;
#pragma unroll
        for (int mt = 0; mt < 2; mt++)
            ldsm4(af[buf][mt],
                  sAb + tA + swz((wm * 32 + mt * 16 + a_row) * 128 + kb + a_cb));
#pragma unroll
        for (int ntp = 0; ntp < 2; ntp++)
            ldsm2x2(bf[buf][2 * ntp], bf[buf][2 * ntp + 1],
                    sBb + tB + swz((wn * 32 + ntp * 16 + b_row) * 128 + kb + b_cb));
    };

    // progressive consumption: chunk c becomes usable at wait_group (3-c)
#pragma unroll
    for (int c = 0; c < 4; c++) {
        switch (c) {
            case 0: cp_wait<3>(); break;
            case 1: cp_wait<2>(); break;
            case 2: cp_wait<1>(); break;
            default: cp_wait<0>(); break;
        }
        __syncthreads();    // forward-only: no smem reuse, just visibility

        fetch(4 * c, 0);
#pragma unroll
        for (int ks = 0; ks < 4; ks++) {
            const int cur = ks & 1;
            if (ks < 3) fetch(4 * c + ks + 1, cur ^ 1);
#pragma unroll
            for (int mt = 0; mt < 2; mt++)
#pragma unroll
                for (int nt = 0; nt < 4; nt++)
                    mma16816(acc[mt][nt], af[cur][mt], bf[cur][nt]);
        }
    }

    const int g = lid >> 2, tig = lid & 3;
#pragma unroll
    for (int mt = 0; mt < 2; mt++) {
#pragma unroll
        for (int nt = 0; nt < 4; nt++) {
            int row = bm * BM + wm * 32 + mt * 16 + g;
            int col = bn * BN + wn * 32 + nt * 8 + 2 * tig;
            *(float2*)(C + (size_t)row * 256 + col) = make_float2(acc[mt][nt][0], acc[mt][nt][1]);
            *(float2*)(C + (size_t)(row + 8) * 256 + col) = make_float2(acc[mt][nt][2], acc[mt][nt][3]);
        }
    }
}

extern "C" void kernel_launch(void* const* d_in, const int* in_sizes, int n_in,
                              void* d_out, int out_size)
{
    const float* x = (const float*)d_in[0];
    const float* W = (const float*)d_in[2];
    float* out = (float*)d_out;

    cvt_all<<<264, 256>>>((const float4*)x, (const float4*)W);

    cudaFuncSetAttribute(gat_gemm5, cudaFuncAttributeMaxDynamicSharedMemorySize, SMEM_TOTAL);
    dim3 grid(256 / BN, 8192 / BM);   // (2, 128) = 256 CTAs
    gat_gemm5<<<grid, THREADS, SMEM_TOTAL>>>(out);
}